// round 15
// baseline (speedup 1.0000x reference)
#include <cuda_runtime.h>
#include <math.h>
#include <stdint.h>

// ---------------- problem constants ----------------
#define B_      2
#define T_      4096
#define DIM_    512
#define H_      8
#define DH_     64
#define NHASH_  8
#define NB_     64
#define BUCKET_ 64
#define NCH_    512          // NHASH * NB
#define BH_     16           // B * H
#define HID_    2048
#define TAGS_   17
#define NT_     32768        // NHASH * T
#define ROWS_   8192         // B * T
#define DEPTH_  2

// ---------------- scratch (device globals; no allocation allowed) ----------------
__device__ float g_x1[ROWS_ * DIM_];
__device__ float g_x2[ROWS_ * DIM_];
__device__ float g_ln[ROWS_ * DIM_];
__device__ float g_qk[ROWS_ * DIM_];
__device__ float g_v [ROWS_ * DIM_];
__device__ float g_attn[ROWS_ * DIM_];
__device__ float g_hid[ROWS_ * HID_];
__device__ int   g_buckets[BH_ * NT_];
__device__ int   g_offsets[BH_ * NCH_];
__device__ int   g_sidx[BH_ * NT_];
__device__ float g_o[(size_t)BH_ * NT_ * DH_];
__device__ float g_lse[BH_ * NT_];

// ---------------- embedding + axial positions ----------------
__global__ void embed_kernel(const int* __restrict__ X, const float* __restrict__ emb,
                             const float* __restrict__ ax1, const float* __restrict__ ax2)
{
    int idx = blockIdx.x * blockDim.x + threadIdx.x;
    if (idx >= ROWS_ * DIM_) return;
    int dcol = idx & (DIM_ - 1);
    int bt   = idx >> 9;
    int t    = bt & (T_ - 1);
    float val = emb[(size_t)X[bt] * DIM_ + dcol];
    if (dcol < 256) val += ax1[(t >> 6) * 256 + dcol];
    else            val += ax2[(t & 63) * 256 + (dcol - 256)];
    g_x1[idx] = val;
    g_x2[idx] = val;
}

// ---------------- layernorm (optionally y = LN(0.5*(x+xb))) ----------------
__global__ void ln_kernel(const float* __restrict__ x, const float* __restrict__ xb,
                          const float* __restrict__ g, const float* __restrict__ bt,
                          float* __restrict__ y)
{
    int row = blockIdx.x;
    int tid = threadIdx.x;           // 128
    const float* xr = x + (size_t)row * DIM_;
    float v[4];
    float s = 0.f;
#pragma unroll
    for (int k = 0; k < 4; k++) {
        int col = tid + 128 * k;
        float val = xr[col];
        if (xb) val = 0.5f * (val + xb[(size_t)row * DIM_ + col]);
        v[k] = val; s += val;
    }
    __shared__ float red[128];
    red[tid] = s; __syncthreads();
    for (int o = 64; o > 0; o >>= 1) { if (tid < o) red[tid] += red[tid + o]; __syncthreads(); }
    float mean = red[0] * (1.0f / DIM_);
    __syncthreads();
    float sq = 0.f;
#pragma unroll
    for (int k = 0; k < 4; k++) { float d = v[k] - mean; sq += d * d; }
    red[tid] = sq; __syncthreads();
    for (int o = 64; o > 0; o >>= 1) { if (tid < o) red[tid] += red[tid + o]; __syncthreads(); }
    float rstd = rsqrtf(red[0] * (1.0f / DIM_) + 1e-5f);
#pragma unroll
    for (int k = 0; k < 4; k++) {
        int col = tid + 128 * k;
        y[(size_t)row * DIM_ + col] = (v[k] - mean) * rstd * g[col] + bt[col];
    }
}

// ---------------- f32x2 packed-FMA helpers (sm_103a) ----------------
__device__ __forceinline__ unsigned long long pack2(float x) {
    unsigned long long r;
    asm("mov.b64 %0, {%1, %1};" : "=l"(r) : "r"(__float_as_uint(x)));
    return r;
}
__device__ __forceinline__ void fma2(unsigned long long& c, unsigned long long a, unsigned long long b) {
    asm("fma.rn.f32x2 %0, %1, %2, %0;" : "+l"(c) : "l"(a), "l"(b));
}
__device__ __forceinline__ void unpack2(unsigned long long p, float& lo, float& hi) {
    uint32_t l, h;
    asm("mov.b64 {%0, %1}, %2;" : "=r"(l), "=r"(h) : "l"(p));
    lo = __uint_as_float(l); hi = __uint_as_float(h);
}

// ---------------- fast fp32 SGEMM (round-11 measured-best, PERMANENTLY FROZEN) ----------------
#define SAPITCH 132
template<bool BIAS, bool GELU, bool ACC>
__global__ __launch_bounds__(256) void sgemm(const float* __restrict__ A,
                                             const float* __restrict__ W,
                                             const float* __restrict__ bias,
                                             float* __restrict__ C,
                                             int M, int N, int K)
{
    __shared__ float As[16][SAPITCH];   // transposed: As[k][m]
    __shared__ float Bs[16][128];       // natural:   Bs[k][n]

    int bn = blockIdx.x * 128, bm = blockIdx.y * 128;
    int tid = threadIdx.x;
    int tx = tid & 15, ty = tid >> 4;

    unsigned long long acc2[8][4];
#pragma unroll
    for (int i = 0; i < 8; i++)
#pragma unroll
        for (int jp = 0; jp < 4; jp++) acc2[i][jp] = 0ULL;

    float4 pa[2], pb[2];
#pragma unroll
    for (int i = 0; i < 2; i++) {
        int idx = tid + 256 * i;
        int arow = idx >> 2, akc = (idx & 3) * 4;
        pa[i] = *(const float4*)&A[(size_t)(bm + arow) * K + akc];
        int bkk = idx >> 5, bn4 = idx & 31;
        pb[i] = *(const float4*)&W[(size_t)bkk * N + bn + bn4 * 4];
    }

    for (int k0 = 0; k0 < K; k0 += 16) {
        __syncthreads();
#pragma unroll
        for (int i = 0; i < 2; i++) {
            int idx = tid + 256 * i;
            int arow = idx >> 2, akc = (idx & 3) * 4;
            As[akc + 0][arow] = pa[i].x;
            As[akc + 1][arow] = pa[i].y;
            As[akc + 2][arow] = pa[i].z;
            As[akc + 3][arow] = pa[i].w;
            int bkk = idx >> 5, bn4 = idx & 31;
            *(float4*)&Bs[bkk][bn4 * 4] = pb[i];
        }
        __syncthreads();
        if (k0 + 16 < K) {
#pragma unroll
            for (int i = 0; i < 2; i++) {
                int idx = tid + 256 * i;
                int arow = idx >> 2, akc = (idx & 3) * 4;
                pa[i] = *(const float4*)&A[(size_t)(bm + arow) * K + k0 + 16 + akc];
                int bkk = idx >> 5, bn4 = idx & 31;
                pb[i] = *(const float4*)&W[(size_t)(k0 + 16 + bkk) * N + bn + bn4 * 4];
            }
        }
#pragma unroll
        for (int kk = 0; kk < 16; kk++) {
            float4 a0 = *(float4*)&As[kk][ty * 4];
            float4 a1 = *(float4*)&As[kk][ty * 4 + 64];
            ulonglong2 b0 = *(ulonglong2*)&Bs[kk][tx * 4];
            ulonglong2 b1 = *(ulonglong2*)&Bs[kk][tx * 4 + 64];
            unsigned long long bp[4] = {b0.x, b0.y, b1.x, b1.y};
            float a[8] = {a0.x, a0.y, a0.z, a0.w, a1.x, a1.y, a1.z, a1.w};
#pragma unroll
            for (int i = 0; i < 8; i++) {
                unsigned long long ap = pack2(a[i]);
#pragma unroll
                for (int jp = 0; jp < 4; jp++) fma2(acc2[i][jp], ap, bp[jp]);
            }
        }
    }

#pragma unroll
    for (int ih = 0; ih < 2; ih++) {
#pragma unroll
        for (int i = 0; i < 4; i++) {
            int m = bm + ty * 4 + ih * 64 + i;
#pragma unroll
            for (int jh = 0; jh < 2; jh++) {
                int n = bn + tx * 4 + jh * 64;
#pragma unroll
                for (int jp = 0; jp < 2; jp++) {
                    float v0, v1;
                    unpack2(acc2[ih * 4 + i][jh * 2 + jp], v0, v1);
                    int nn = n + jp * 2;
                    if (BIAS) { v0 += bias[nn]; v1 += bias[nn + 1]; }
                    if (GELU) {
                        float x = v0;
                        v0 = 0.5f * x * (1.f + tanhf(0.7978845608028654f * (x + 0.044715f * x * x * x)));
                        x = v1;
                        v1 = 0.5f * x * (1.f + tanhf(0.7978845608028654f * (x + 0.044715f * x * x * x)));
                    }
                    size_t idx = (size_t)m * N + nn;
                    if (ACC) { C[idx] += v0; C[idx + 1] += v1; }
                    else     { C[idx]  = v0; C[idx + 1]  = v1; }
                }
            }
        }
    }
}

// ---------------- scalar GEMM (only used for N=17 output head) ----------------
template<bool BIAS>
__global__ void gemm_small(const float* __restrict__ A, const float* __restrict__ W,
                           const float* __restrict__ bias, float* __restrict__ C,
                           int M, int N, int K)
{
    __shared__ float As[64][17];
    __shared__ float Bs[16][65];
    int bn = blockIdx.x * 64, bm = blockIdx.y * 64;
    int tid = threadIdx.x;
    int tx = tid & 15, ty = tid >> 4;
    int m0 = ty * 4, n0 = tx * 4;
    float acc[4][4] = {};
    for (int k0 = 0; k0 < K; k0 += 16) {
#pragma unroll
        for (int i = 0; i < 4; i++) {
            int e = tid + 256 * i;
            int m = e >> 4, k = e & 15;
            As[m][k] = A[(size_t)(bm + m) * K + k0 + k];
            int kb = e >> 6, nb = e & 63;
            float w = 0.f;
            if (bn + nb < N) w = W[(size_t)(k0 + kb) * N + bn + nb];
            Bs[kb][nb] = w;
        }
        __syncthreads();
#pragma unroll
        for (int k = 0; k < 16; k++) {
            float a[4], b[4];
#pragma unroll
            for (int i = 0; i < 4; i++) a[i] = As[m0 + i][k];
#pragma unroll
            for (int j = 0; j < 4; j++) b[j] = Bs[k][n0 + j];
#pragma unroll
            for (int i = 0; i < 4; i++)
#pragma unroll
                for (int j = 0; j < 4; j++) acc[i][j] += a[i] * b[j];
        }
        __syncthreads();
    }
#pragma unroll
    for (int i = 0; i < 4; i++) {
        int m = bm + m0 + i;
#pragma unroll
        for (int j = 0; j < 4; j++) {
            int n = bn + n0 + j;
            if (n < N) {
                float val = acc[i][j];
                if (BIAS) val += bias[n];
                C[(size_t)m * N + n] = val;
            }
        }
    }
}

// ---------------- LSH bucketing v3 (validated round 10, FROZEN) ----------------
__global__ void bucket_kernel(const float* __restrict__ rot)
{
    int idx = blockIdx.x * blockDim.x + threadIdx.x;   // BH_*NHASH_*T_
    if (idx >= BH_ * NHASH_ * T_) return;
    int t  = idx & (T_ - 1);
    int h  = (idx >> 12) & (NHASH_ - 1);
    int bh = idx >> 15;
    int b = bh >> 3, head = bh & 7;
    const float* q = g_qk + ((size_t)(b * T_ + t)) * DIM_ + head * DH_;

    float acc[32];
#pragma unroll
    for (int r = 0; r < 32; r++) acc[r] = 0.f;

#pragma unroll
    for (int d4 = 0; d4 < 16; d4++) {
        float4 q4 = *(const float4*)&q[d4 * 4];
#pragma unroll
        for (int dd = 0; dd < 4; dd++) {
            float qd = (dd == 0) ? q4.x : (dd == 1) ? q4.y : (dd == 2) ? q4.z : q4.w;
            const float4* rp = (const float4*)(rot + ((size_t)(d4 * 4 + dd) * NHASH_ + h) * 32);
#pragma unroll
            for (int r4 = 0; r4 < 8; r4++) {
                float4 rv = rp[r4];
                acc[r4 * 4 + 0] += qd * rv.x;
                acc[r4 * 4 + 1] += qd * rv.y;
                acc[r4 * 4 + 2] += qd * rv.z;
                acc[r4 * 4 + 3] += qd * rv.w;
            }
        }
    }

    float best = acc[0]; int bi = 0;
#pragma unroll
    for (int r = 1; r < 32; r++) if (acc[r] > best) { best = acc[r]; bi = r; }
#pragma unroll
    for (int r = 0; r < 32; r++) { float v2 = -acc[r]; if (v2 > best) { best = v2; bi = r + 32; } }
    g_buckets[bh * NT_ + h * T_ + t] = bi + h * NB_;
}

// ---------------- histogram + parallel exclusive scan per bh ----------------
__global__ void hist_kernel()
{
    int bh = blockIdx.x;
    __shared__ int cnt[NCH_];
    __shared__ int scn[NCH_];
    int tid = threadIdx.x;                 // 512
    cnt[tid] = 0;
    __syncthreads();
    const int* bp = g_buckets + bh * NT_;
    for (int i = tid; i < NT_; i += NCH_) atomicAdd(&cnt[bp[i]], 1);
    __syncthreads();
    int own = cnt[tid];
    scn[tid] = own;
    __syncthreads();
    for (int o = 1; o < NCH_; o <<= 1) {
        int add = (tid >= o) ? scn[tid - o] : 0;
        __syncthreads();
        scn[tid] += add;
        __syncthreads();
    }
    g_offsets[bh * NCH_ + tid] = scn[tid] - own;   // exclusive
}

// ---------------- stable scatter: one WARP per (bh, global bucket) ----------------
__global__ void scatter_kernel()
{
    int w = (blockIdx.x * blockDim.x + threadIdx.x) >> 5;   // BH_*NCH_ warps
    int lane = threadIdx.x & 31;
    if (w >= BH_ * NCH_) return;
    int bh = w >> 9, gb = w & (NCH_ - 1);
    int h = gb >> 6;
    int pos = g_offsets[bh * NCH_ + gb];
    const int* bk = g_buckets + bh * NT_ + h * T_;
    int base = bh * NT_;
    for (int t0 = 0; t0 < T_; t0 += 32) {
        int t = t0 + lane;
        bool m = (bk[t] == gb);
        unsigned mask = __ballot_sync(0xffffffffu, m);
        if (m) {
            int r = __popc(mask & ((1u << lane) - 1u));
            g_sidx[base + pos + r] = h * T_ + t;
        }
        pos += __popc(mask);
    }
}

// ---------------- chunked LSH attention v5 (validated round 14, FROZEN) ----------------
__global__ __launch_bounds__(256, 2) void attn_kernel()
{
    extern __shared__ float sm[];
    float* sk   = sm;                       // 128*65 raw qk rows
    float* sv   = sk + 128 * 65;            // 128*65
    float* sp   = sv + 128 * 65;            // 64*129
    float* rn   = sp + 64 * 129;            // 128 inverse key norms
    float* slse = rn + 128;                 // 64
    int*   sqt  = (int*)(slse + 64);        // 64
    int*   skt  = sqt + 64;                 // 128

    int c  = blockIdx.x;
    int bh = blockIdx.y;
    int b = bh >> 3, head = bh & 7;
    int tid = threadIdx.x;                  // 256
    int w = tid >> 5, L = tid & 31;
    const int* sidx_bh = g_sidx + bh * NT_;
    int pc = (c + NCH_ - 1) & (NCH_ - 1);

    if (tid < 64) {
        int si = sidx_bh[c * BUCKET_ + tid];
        sqt[tid] = si;
        skt[tid] = si & (T_ - 1);
    } else if (tid < 128) {
        int si = sidx_bh[pc * BUCKET_ + (tid - 64)];
        skt[tid] = si & (T_ - 1);
    }
    __syncthreads();

    for (int e = tid; e < 128 * 16; e += 256) {
        int j = e >> 4, d4 = e & 15;
        size_t base = ((size_t)(b * T_ + skt[j])) * DIM_ + head * DH_ + d4 * 4;
        float4 kq = *(const float4*)&g_qk[base];
        float4 vv = *(const float4*)&g_v[base];
        int o = j * 65 + d4 * 4;
        sk[o + 0] = kq.x; sk[o + 1] = kq.y; sk[o + 2] = kq.z; sk[o + 3] = kq.w;
        sv[o + 0] = vv.x; sv[o + 1] = vv.y; sv[o + 2] = vv.z; sv[o + 3] = vv.w;
    }
    __syncthreads();

    if (tid < 128) {
        float s = 0.f;
#pragma unroll
        for (int d = 0; d < 64; d++) { float x = sk[tid * 65 + d]; s += x * x; }
        rn[tid] = rsqrtf(s);
    }
    __syncthreads();

#pragma unroll
    for (int p = 0; p < 2; p++) {
        int i0 = w + 8 * p;
        float acc[4][4];
#pragma unroll
        for (int ii = 0; ii < 4; ii++)
#pragma unroll
            for (int jj = 0; jj < 4; jj++) acc[ii][jj] = 0.f;
        for (int d = 0; d < 64; d++) {
            float qv[4], kv[4];
#pragma unroll
            for (int ii = 0; ii < 4; ii++) qv[ii] = sk[(i0 + 16 * ii) * 65 + d];
#pragma unroll
            for (int jj = 0; jj < 4; jj++) kv[jj] = sk[(L + 32 * jj) * 65 + d];
#pragma unroll
            for (int ii = 0; ii < 4; ii++)
#pragma unroll
                for (int jj = 0; jj < 4; jj++) acc[ii][jj] += qv[ii] * kv[jj];
        }
        float rsc[4];
#pragma unroll
        for (int jj = 0; jj < 4; jj++) rsc[jj] = rn[L + 32 * jj] * 0.125f;
#pragma unroll
        for (int ii = 0; ii < 4; ii++) {
            int i = i0 + 16 * ii;
            int ti = skt[i];
#pragma unroll
            for (int jj = 0; jj < 4; jj++) {
                int j = L + 32 * jj;
                float s = acc[ii][jj] * rsc[jj];
                if (ti == skt[j]) s = -5e4f;
                sp[i * 129 + j] = s;
            }
        }
    }
    __syncthreads();

    // warp-parallel row softmax + lse
#pragma unroll
    for (int r = 0; r < 8; r++) {
        int i = w + 8 * r;
        float v[4];
#pragma unroll
        for (int q = 0; q < 4; q++) v[q] = sp[i * 129 + L + 32 * q];
        float m = fmaxf(fmaxf(v[0], v[1]), fmaxf(v[2], v[3]));
#pragma unroll
        for (int o = 16; o > 0; o >>= 1) m = fmaxf(m, __shfl_xor_sync(0xffffffffu, m, o));
        float s = 0.f;
#pragma unroll
        for (int q = 0; q < 4; q++) { v[q] = expf(v[q] - m); s += v[q]; }
#pragma unroll
        for (int o = 16; o > 0; o >>= 1) s += __shfl_xor_sync(0xffffffffu, s, o);
        float inv = 1.f / s;
#pragma unroll
        for (int q = 0; q < 4; q++) sp[i * 129 + L + 32 * q] = v[q] * inv;
        if (L == 0) slse[i] = m + logf(s);
    }
    __syncthreads();

#pragma unroll
    for (int p = 0; p < 2; p++) {
        int i0 = w + 8 * p;
        float a0[4], a1[4];
#pragma unroll
        for (int ii = 0; ii < 4; ii++) { a0[ii] = 0.f; a1[ii] = 0.f; }
        for (int j = 0; j < 128; j++) {
            float v0 = sv[j * 65 + L];
            float v1 = sv[j * 65 + L + 32];
#pragma unroll
            for (int ii = 0; ii < 4; ii++) {
                float pv = sp[(i0 + 16 * ii) * 129 + j];
                a0[ii] += pv * v0;
                a1[ii] += pv * v1;
            }
        }
#pragma unroll
        for (int ii = 0; ii < 4; ii++) {
            int i = i0 + 16 * ii;
            size_t ob = ((size_t)bh * NT_ + sqt[i]) * DH_;
            g_o[ob + L]      = a0[ii];
            g_o[ob + L + 32] = a1[ii];
        }
    }
    if (tid < 64) g_lse[(size_t)bh * NT_ + sqt[tid]] = slse[tid];
}

// ---------------- combine NHASH rounds (softmax over lse weights) ----------------
__global__ void combine_kernel()
{
    int gtid = blockIdx.x * blockDim.x + threadIdx.x;
    int w = gtid >> 5;
    int lane = gtid & 31;
    if (w >= BH_ * T_) return;
    int bh = w >> 12, t = w & (T_ - 1);
    int b = bh >> 3, head = bh & 7;
    float l[NHASH_];
    float m = -1e30f;
#pragma unroll
    for (int h = 0; h < NHASH_; h++) { l[h] = g_lse[(size_t)bh * NT_ + h * T_ + t]; m = fmaxf(m, l[h]); }
    float s = 0.f;
#pragma unroll
    for (int h = 0; h < NHASH_; h++) { l[h] = expf(l[h] - m); s += l[h]; }
    float inv = 1.f / s;
#pragma unroll
    for (int k = 0; k < 2; k++) {
        int d = lane + 32 * k;
        float acc = 0.f;
#pragma unroll
        for (int h = 0; h < NHASH_; h++)
            acc += l[h] * g_o[((size_t)bh * NT_ + h * T_ + t) * DH_ + d];
        g_attn[((size_t)(b * T_ + t)) * DIM_ + head * DH_ + d] = acc * inv;
    }
}

// ---------------- host launch ----------------
extern "C" void kernel_launch(void* const* d_in, const int* in_sizes, int n_in,
                              void* d_out, int out_size)
{
    (void)in_sizes; (void)n_in; (void)out_size;
    const int*   X    = (const int*)  d_in[0];
    const float* emb  = (const float*)d_in[1];
    const float* ax1  = (const float*)d_in[2];
    const float* ax2  = (const float*)d_in[3];
    const float* Wqk  = (const float*)d_in[4];
    const float* Wv   = (const float*)d_in[5];
    const float* Wo   = (const float*)d_in[6];
    const float* ln1g = (const float*)d_in[7];
    const float* ln1b = (const float*)d_in[8];
    const float* W1   = (const float*)d_in[9];
    const float* b1   = (const float*)d_in[10];
    const float* W2   = (const float*)d_in[11];
    const float* b2   = (const float*)d_in[12];
    const float* ln2g = (const float*)d_in[13];
    const float* ln2b = (const float*)d_in[14];
    const float* lnfg = (const float*)d_in[15];
    const float* lnfb = (const float*)d_in[16];
    const float* Wout = (const float*)d_in[17];
    const float* bout = (const float*)d_in[18];
    const float* rot  = (const float*)d_in[19];
    float* out = (float*)d_out;

    float *x1, *x2, *ln, *hid, *attn;
    cudaGetSymbolAddress((void**)&x1,   g_x1);
    cudaGetSymbolAddress((void**)&x2,   g_x2);
    cudaGetSymbolAddress((void**)&ln,   g_ln);
    cudaGetSymbolAddress((void**)&hid,  g_hid);
    cudaGetSymbolAddress((void**)&attn, g_attn);
    float *qkp, *vp;
    cudaGetSymbolAddress((void**)&qkp, g_qk);
    cudaGetSymbolAddress((void**)&vp,  g_v);

    const size_t ATTN_SMEM =
        (size_t)(2 * 128 * 65 + 64 * 129 + 128 + 64) * sizeof(float) + (64 + 128) * sizeof(int);
    cudaFuncSetAttribute(attn_kernel, cudaFuncAttributeMaxDynamicSharedMemorySize, (int)ATTN_SMEM);

    // side stream + fork/join events (no device memory involved; graph-capture
    // stream forks via event record/wait are the standard capture pattern)
    cudaStream_t s1;
    cudaStreamCreateWithFlags(&s1, cudaStreamNonBlocking);
    cudaEvent_t evFork[DEPTH_], evJoin[DEPTH_];
    for (int l = 0; l < DEPTH_; l++) {
        cudaEventCreateWithFlags(&evFork[l], cudaEventDisableTiming);
        cudaEventCreateWithFlags(&evJoin[l], cudaEventDisableTiming);
    }

    embed_kernel<<<(ROWS_ * DIM_) / 256, 256>>>(X, emb, ax1, ax2);

    for (int l = 0; l < DEPTH_; l++) {
        const float* Wqk_l = Wqk + (size_t)l * DIM_ * DIM_;
        const float* Wv_l  = Wv  + (size_t)l * DIM_ * DIM_;
        const float* Wo_l  = Wo  + (size_t)l * DIM_ * DIM_;
        const float* W1_l  = W1  + (size_t)l * DIM_ * HID_;
        const float* b1_l  = b1  + (size_t)l * HID_;
        const float* W2_l  = W2  + (size_t)l * HID_ * DIM_;
        const float* b2_l  = b2  + (size_t)l * DIM_;
        const float* rot_l = rot + (size_t)l * DH_ * NHASH_ * 32;

        // ---- attention: x1 += Attn(LN(x2)) @ Wo ----
        ln_kernel<<<ROWS_, 128>>>(x2, nullptr, ln1g + l * DIM_, ln1b + l * DIM_, ln);

        // fork: Wv on s1 runs concurrently with Wqk + bucket/hist/scatter chain
        cudaEventRecord(evFork[l], 0);
        cudaStreamWaitEvent(s1, evFork[l], 0);
        {
            dim3 grid(DIM_ / 128, ROWS_ / 128);
            sgemm<false, false, false><<<grid, 256, 0, s1>>>(ln, Wv_l, nullptr, vp, ROWS_, DIM_, DIM_);
            sgemm<false, false, false><<<grid, 256>>>(ln, Wqk_l, nullptr, qkp, ROWS_, DIM_, DIM_);
        }
        bucket_kernel<<<(BH_ * NHASH_ * T_) / 256, 256>>>(rot_l);
        hist_kernel<<<BH_, NCH_>>>();
        scatter_kernel<<<(BH_ * NCH_ * 32) / 256, 256>>>();
        // join: attn needs g_v
        cudaEventRecord(evJoin[l], s1);
        cudaStreamWaitEvent(0, evJoin[l], 0);

        attn_kernel<<<dim3(NCH_, BH_), 256, ATTN_SMEM>>>();
        combine_kernel<<<(BH_ * T_ * 32) / 256, 256>>>();
        {
            dim3 grid(DIM_ / 128, ROWS_ / 128);
            sgemm<false, false, true><<<grid, 256>>>(attn, Wo_l, nullptr, x1, ROWS_, DIM_, DIM_);
        }

        // ---- feed-forward: x2 += W2 @ gelu(W1 @ LN(x1) + b1) + b2 ----
        ln_kernel<<<ROWS_, 128>>>(x1, nullptr, ln2g + l * DIM_, ln2b + l * DIM_, ln);
        {
            dim3 grid1(HID_ / 128, ROWS_ / 128);
            sgemm<true, true, false><<<grid1, 256>>>(ln, W1_l, b1_l, hid, ROWS_, HID_, DIM_);
            dim3 grid2(DIM_ / 128, ROWS_ / 128);
            sgemm<true, false, true><<<grid2, 256>>>(hid, W2_l, b2_l, x2, ROWS_, DIM_, HID_);
        }
    }

    // final: LN(0.5*(x1+x2)) @ Wout + bout
    ln_kernel<<<ROWS_, 128>>>(x1, x2, lnfg, lnfb, ln);
    {
        dim3 grid((TAGS_ + 63) / 64, ROWS_ / 64);
        gemm_small<true><<<grid, 256>>>(ln, Wout, bout, out, ROWS_, TAGS_, DIM_);
    }
}

// round 16
// speedup vs baseline: 1.0797x; 1.0797x over previous
#include <cuda_runtime.h>
#include <math.h>
#include <stdint.h>

// ---------------- problem constants ----------------
#define B_      2
#define T_      4096
#define DIM_    512
#define H_      8
#define DH_     64
#define NHASH_  8
#define NB_     64
#define BUCKET_ 64
#define NCH_    512          // NHASH * NB
#define BH_     16           // B * H
#define HID_    2048
#define TAGS_   17
#define NT_     32768        // NHASH * T
#define ROWS_   8192         // B * T
#define DEPTH_  2

// ---------------- scratch (device globals; no allocation allowed) ----------------
__device__ float g_x1[ROWS_ * DIM_];
__device__ float g_x2[ROWS_ * DIM_];
__device__ float g_ln[ROWS_ * DIM_];
__device__ float g_qk[ROWS_ * DIM_];
__device__ float g_v [ROWS_ * DIM_];
__device__ float g_attn[ROWS_ * DIM_];
__device__ float g_hid[ROWS_ * HID_];
__device__ int   g_buckets[BH_ * NT_];
__device__ int   g_offsets[BH_ * NCH_];
__device__ int   g_sidx[BH_ * NT_];
__device__ float g_o[(size_t)BH_ * NT_ * DH_];
__device__ float g_lse[BH_ * NT_];

// ---------------- embedding + axial positions ----------------
__global__ void embed_kernel(const int* __restrict__ X, const float* __restrict__ emb,
                             const float* __restrict__ ax1, const float* __restrict__ ax2)
{
    int idx = blockIdx.x * blockDim.x + threadIdx.x;
    if (idx >= ROWS_ * DIM_) return;
    int dcol = idx & (DIM_ - 1);
    int bt   = idx >> 9;
    int t    = bt & (T_ - 1);
    float val = emb[(size_t)X[bt] * DIM_ + dcol];
    if (dcol < 256) val += ax1[(t >> 6) * 256 + dcol];
    else            val += ax2[(t & 63) * 256 + (dcol - 256)];
    g_x1[idx] = val;
    g_x2[idx] = val;
}

// ---------------- layernorm (optionally y = LN(0.5*(x+xb))) ----------------
__global__ void ln_kernel(const float* __restrict__ x, const float* __restrict__ xb,
                          const float* __restrict__ g, const float* __restrict__ bt,
                          float* __restrict__ y)
{
    int row = blockIdx.x;
    int tid = threadIdx.x;           // 128
    const float* xr = x + (size_t)row * DIM_;
    float v[4];
    float s = 0.f;
#pragma unroll
    for (int k = 0; k < 4; k++) {
        int col = tid + 128 * k;
        float val = xr[col];
        if (xb) val = 0.5f * (val + xb[(size_t)row * DIM_ + col]);
        v[k] = val; s += val;
    }
    __shared__ float red[128];
    red[tid] = s; __syncthreads();
    for (int o = 64; o > 0; o >>= 1) { if (tid < o) red[tid] += red[tid + o]; __syncthreads(); }
    float mean = red[0] * (1.0f / DIM_);
    __syncthreads();
    float sq = 0.f;
#pragma unroll
    for (int k = 0; k < 4; k++) { float d = v[k] - mean; sq += d * d; }
    red[tid] = sq; __syncthreads();
    for (int o = 64; o > 0; o >>= 1) { if (tid < o) red[tid] += red[tid + o]; __syncthreads(); }
    float rstd = rsqrtf(red[0] * (1.0f / DIM_) + 1e-5f);
#pragma unroll
    for (int k = 0; k < 4; k++) {
        int col = tid + 128 * k;
        y[(size_t)row * DIM_ + col] = (v[k] - mean) * rstd * g[col] + bt[col];
    }
}

// ---------------- f32x2 packed-FMA helpers (sm_103a) ----------------
__device__ __forceinline__ unsigned long long pack2(float x) {
    unsigned long long r;
    asm("mov.b64 %0, {%1, %1};" : "=l"(r) : "r"(__float_as_uint(x)));
    return r;
}
__device__ __forceinline__ void fma2(unsigned long long& c, unsigned long long a, unsigned long long b) {
    asm("fma.rn.f32x2 %0, %1, %2, %0;" : "+l"(c) : "l"(a), "l"(b));
}
__device__ __forceinline__ void unpack2(unsigned long long p, float& lo, float& hi) {
    uint32_t l, h;
    asm("mov.b64 {%0, %1}, %2;" : "=r"(l), "=r"(h) : "l"(p));
    lo = __uint_as_float(l); hi = __uint_as_float(h);
}

// ---------------- fast fp32 SGEMM (round-11 core, FROZEN numerics) + optional z-merge ----------------
// If DUAL, blockIdx.z==1 uses Wb/Cb (two independent GEMMs sharing A in one launch).
#define SAPITCH 132
template<bool BIAS, bool GELU, bool ACC, bool DUAL>
__global__ __launch_bounds__(256) void sgemm(const float* __restrict__ A,
                                             const float* __restrict__ W,
                                             const float* __restrict__ bias,
                                             float* __restrict__ C,
                                             const float* __restrict__ Wb,
                                             float* __restrict__ Cb,
                                             int M, int N, int K)
{
    if (DUAL && blockIdx.z) { W = Wb; C = Cb; }

    __shared__ float As[16][SAPITCH];   // transposed: As[k][m]
    __shared__ float Bs[16][128];       // natural:   Bs[k][n]

    int bn = blockIdx.x * 128, bm = blockIdx.y * 128;
    int tid = threadIdx.x;
    int tx = tid & 15, ty = tid >> 4;

    unsigned long long acc2[8][4];
#pragma unroll
    for (int i = 0; i < 8; i++)
#pragma unroll
        for (int jp = 0; jp < 4; jp++) acc2[i][jp] = 0ULL;

    float4 pa[2], pb[2];
#pragma unroll
    for (int i = 0; i < 2; i++) {
        int idx = tid + 256 * i;
        int arow = idx >> 2, akc = (idx & 3) * 4;
        pa[i] = *(const float4*)&A[(size_t)(bm + arow) * K + akc];
        int bkk = idx >> 5, bn4 = idx & 31;
        pb[i] = *(const float4*)&W[(size_t)bkk * N + bn + bn4 * 4];
    }

    for (int k0 = 0; k0 < K; k0 += 16) {
        __syncthreads();
#pragma unroll
        for (int i = 0; i < 2; i++) {
            int idx = tid + 256 * i;
            int arow = idx >> 2, akc = (idx & 3) * 4;
            As[akc + 0][arow] = pa[i].x;
            As[akc + 1][arow] = pa[i].y;
            As[akc + 2][arow] = pa[i].z;
            As[akc + 3][arow] = pa[i].w;
            int bkk = idx >> 5, bn4 = idx & 31;
            *(float4*)&Bs[bkk][bn4 * 4] = pb[i];
        }
        __syncthreads();
        if (k0 + 16 < K) {
#pragma unroll
            for (int i = 0; i < 2; i++) {
                int idx = tid + 256 * i;
                int arow = idx >> 2, akc = (idx & 3) * 4;
                pa[i] = *(const float4*)&A[(size_t)(bm + arow) * K + k0 + 16 + akc];
                int bkk = idx >> 5, bn4 = idx & 31;
                pb[i] = *(const float4*)&W[(size_t)(k0 + 16 + bkk) * N + bn + bn4 * 4];
            }
        }
#pragma unroll
        for (int kk = 0; kk < 16; kk++) {
            float4 a0 = *(float4*)&As[kk][ty * 4];
            float4 a1 = *(float4*)&As[kk][ty * 4 + 64];
            ulonglong2 b0 = *(ulonglong2*)&Bs[kk][tx * 4];
            ulonglong2 b1 = *(ulonglong2*)&Bs[kk][tx * 4 + 64];
            unsigned long long bp[4] = {b0.x, b0.y, b1.x, b1.y};
            float a[8] = {a0.x, a0.y, a0.z, a0.w, a1.x, a1.y, a1.z, a1.w};
#pragma unroll
            for (int i = 0; i < 8; i++) {
                unsigned long long ap = pack2(a[i]);
#pragma unroll
                for (int jp = 0; jp < 4; jp++) fma2(acc2[i][jp], ap, bp[jp]);
            }
        }
    }

#pragma unroll
    for (int ih = 0; ih < 2; ih++) {
#pragma unroll
        for (int i = 0; i < 4; i++) {
            int m = bm + ty * 4 + ih * 64 + i;
#pragma unroll
            for (int jh = 0; jh < 2; jh++) {
                int n = bn + tx * 4 + jh * 64;
#pragma unroll
                for (int jp = 0; jp < 2; jp++) {
                    float v0, v1;
                    unpack2(acc2[ih * 4 + i][jh * 2 + jp], v0, v1);
                    int nn = n + jp * 2;
                    if (BIAS) { v0 += bias[nn]; v1 += bias[nn + 1]; }
                    if (GELU) {
                        float x = v0;
                        v0 = 0.5f * x * (1.f + tanhf(0.7978845608028654f * (x + 0.044715f * x * x * x)));
                        x = v1;
                        v1 = 0.5f * x * (1.f + tanhf(0.7978845608028654f * (x + 0.044715f * x * x * x)));
                    }
                    size_t idx = (size_t)m * N + nn;
                    if (ACC) { C[idx] += v0; C[idx + 1] += v1; }
                    else     { C[idx]  = v0; C[idx + 1]  = v1; }
                }
            }
        }
    }
}

// ---------------- scalar GEMM (only used for N=17 output head) ----------------
template<bool BIAS>
__global__ void gemm_small(const float* __restrict__ A, const float* __restrict__ W,
                           const float* __restrict__ bias, float* __restrict__ C,
                           int M, int N, int K)
{
    __shared__ float As[64][17];
    __shared__ float Bs[16][65];
    int bn = blockIdx.x * 64, bm = blockIdx.y * 64;
    int tid = threadIdx.x;
    int tx = tid & 15, ty = tid >> 4;
    int m0 = ty * 4, n0 = tx * 4;
    float acc[4][4] = {};
    for (int k0 = 0; k0 < K; k0 += 16) {
#pragma unroll
        for (int i = 0; i < 4; i++) {
            int e = tid + 256 * i;
            int m = e >> 4, k = e & 15;
            As[m][k] = A[(size_t)(bm + m) * K + k0 + k];
            int kb = e >> 6, nb = e & 63;
            float w = 0.f;
            if (bn + nb < N) w = W[(size_t)(k0 + kb) * N + bn + nb];
            Bs[kb][nb] = w;
        }
        __syncthreads();
#pragma unroll
        for (int k = 0; k < 16; k++) {
            float a[4], b[4];
#pragma unroll
            for (int i = 0; i < 4; i++) a[i] = As[m0 + i][k];
#pragma unroll
            for (int j = 0; j < 4; j++) b[j] = Bs[k][n0 + j];
#pragma unroll
            for (int i = 0; i < 4; i++)
#pragma unroll
                for (int j = 0; j < 4; j++) acc[i][j] += a[i] * b[j];
        }
        __syncthreads();
    }
#pragma unroll
    for (int i = 0; i < 4; i++) {
        int m = bm + m0 + i;
#pragma unroll
        for (int j = 0; j < 4; j++) {
            int n = bn + n0 + j;
            if (n < N) {
                float val = acc[i][j];
                if (BIAS) val += bias[n];
                C[(size_t)m * N + n] = val;
            }
        }
    }
}

// ---------------- LSH bucketing v3 (validated round 10, FROZEN) ----------------
__global__ void bucket_kernel(const float* __restrict__ rot)
{
    int idx = blockIdx.x * blockDim.x + threadIdx.x;   // BH_*NHASH_*T_
    if (idx >= BH_ * NHASH_ * T_) return;
    int t  = idx & (T_ - 1);
    int h  = (idx >> 12) & (NHASH_ - 1);
    int bh = idx >> 15;
    int b = bh >> 3, head = bh & 7;
    const float* q = g_qk + ((size_t)(b * T_ + t)) * DIM_ + head * DH_;

    float acc[32];
#pragma unroll
    for (int r = 0; r < 32; r++) acc[r] = 0.f;

#pragma unroll
    for (int d4 = 0; d4 < 16; d4++) {
        float4 q4 = *(const float4*)&q[d4 * 4];
#pragma unroll
        for (int dd = 0; dd < 4; dd++) {
            float qd = (dd == 0) ? q4.x : (dd == 1) ? q4.y : (dd == 2) ? q4.z : q4.w;
            const float4* rp = (const float4*)(rot + ((size_t)(d4 * 4 + dd) * NHASH_ + h) * 32);
#pragma unroll
            for (int r4 = 0; r4 < 8; r4++) {
                float4 rv = rp[r4];
                acc[r4 * 4 + 0] += qd * rv.x;
                acc[r4 * 4 + 1] += qd * rv.y;
                acc[r4 * 4 + 2] += qd * rv.z;
                acc[r4 * 4 + 3] += qd * rv.w;
            }
        }
    }

    float best = acc[0]; int bi = 0;
#pragma unroll
    for (int r = 1; r < 32; r++) if (acc[r] > best) { best = acc[r]; bi = r; }
#pragma unroll
    for (int r = 0; r < 32; r++) { float v2 = -acc[r]; if (v2 > best) { best = v2; bi = r + 32; } }
    g_buckets[bh * NT_ + h * T_ + t] = bi + h * NB_;
}

// ---------------- histogram + parallel exclusive scan per bh ----------------
__global__ void hist_kernel()
{
    int bh = blockIdx.x;
    __shared__ int cnt[NCH_];
    __shared__ int scn[NCH_];
    int tid = threadIdx.x;                 // 512
    cnt[tid] = 0;
    __syncthreads();
    const int* bp = g_buckets + bh * NT_;
    for (int i = tid; i < NT_; i += NCH_) atomicAdd(&cnt[bp[i]], 1);
    __syncthreads();
    int own = cnt[tid];
    scn[tid] = own;
    __syncthreads();
    for (int o = 1; o < NCH_; o <<= 1) {
        int add = (tid >= o) ? scn[tid - o] : 0;
        __syncthreads();
        scn[tid] += add;
        __syncthreads();
    }
    g_offsets[bh * NCH_ + tid] = scn[tid] - own;   // exclusive
}

// ---------------- stable scatter: one WARP per (bh, global bucket) ----------------
__global__ void scatter_kernel()
{
    int w = (blockIdx.x * blockDim.x + threadIdx.x) >> 5;   // BH_*NCH_ warps
    int lane = threadIdx.x & 31;
    if (w >= BH_ * NCH_) return;
    int bh = w >> 9, gb = w & (NCH_ - 1);
    int h = gb >> 6;
    int pos = g_offsets[bh * NCH_ + gb];
    const int* bk = g_buckets + bh * NT_ + h * T_;
    int base = bh * NT_;
    for (int t0 = 0; t0 < T_; t0 += 32) {
        int t = t0 + lane;
        bool m = (bk[t] == gb);
        unsigned mask = __ballot_sync(0xffffffffu, m);
        if (m) {
            int r = __popc(mask & ((1u << lane) - 1u));
            g_sidx[base + pos + r] = h * T_ + t;
        }
        pos += __popc(mask);
    }
}

// ---------------- chunked LSH attention v6: v5 + float2-vectorized LDS ----------------
// Pitches 66 (sk/sv) and 130 (sp) so rows are 8B-aligned. All accumulations stay
// strictly d-ascending / j-ascending scalar fp32 FMA => bit-exact vs v5.
#define KPITCH 66
#define PPITCH 130
__global__ __launch_bounds__(256, 2) void attn_kernel()
{
    extern __shared__ float sm[];
    float* sk   = sm;                        // 128*66 raw qk rows
    float* sv   = sk + 128 * KPITCH;         // 128*66
    float* sp   = sv + 128 * KPITCH;         // 64*130
    float* rn   = sp + 64 * PPITCH;          // 128 inverse key norms
    float* slse = rn + 128;                  // 64
    int*   sqt  = (int*)(slse + 64);         // 64
    int*   skt  = sqt + 64;                  // 128

    int c  = blockIdx.x;
    int bh = blockIdx.y;
    int b = bh >> 3, head = bh & 7;
    int tid = threadIdx.x;                   // 256
    int w = tid >> 5, L = tid & 31;
    const int* sidx_bh = g_sidx + bh * NT_;
    int pc = (c + NCH_ - 1) & (NCH_ - 1);

    if (tid < 64) {
        int si = sidx_bh[c * BUCKET_ + tid];
        sqt[tid] = si;
        skt[tid] = si & (T_ - 1);
    } else if (tid < 128) {
        int si = sidx_bh[pc * BUCKET_ + (tid - 64)];
        skt[tid] = si & (T_ - 1);
    }
    __syncthreads();

    // gather k and v rows (128 x 64): float4 LDG + float2 STS (rows 8B-aligned)
    for (int e = tid; e < 128 * 16; e += 256) {
        int j = e >> 4, d4 = e & 15;
        size_t base = ((size_t)(b * T_ + skt[j])) * DIM_ + head * DH_ + d4 * 4;
        float4 kq = *(const float4*)&g_qk[base];
        float4 vv = *(const float4*)&g_v[base];
        int o = j * KPITCH + d4 * 4;
        *(float2*)&sk[o]     = make_float2(kq.x, kq.y);
        *(float2*)&sk[o + 2] = make_float2(kq.z, kq.w);
        *(float2*)&sv[o]     = make_float2(vv.x, vv.y);
        *(float2*)&sv[o + 2] = make_float2(vv.z, vv.w);
    }
    __syncthreads();

    // inverse key norms (scalar d-ascending, unchanged)
    if (tid < 128) {
        float s = 0.f;
#pragma unroll
        for (int d = 0; d < 64; d++) { float x = sk[tid * KPITCH + d]; s += x * x; }
        rn[tid] = rsqrtf(s);
    }
    __syncthreads();

    // dots: float2 loads over d; per-(ii,jj) accumulation stays d-ascending
#pragma unroll
    for (int p = 0; p < 2; p++) {
        int i0 = w + 8 * p;
        float acc[4][4];
#pragma unroll
        for (int ii = 0; ii < 4; ii++)
#pragma unroll
            for (int jj = 0; jj < 4; jj++) acc[ii][jj] = 0.f;
        for (int dh = 0; dh < 32; dh++) {
            float2 qv[4], kv[4];
#pragma unroll
            for (int ii = 0; ii < 4; ii++) qv[ii] = *(float2*)&sk[(i0 + 16 * ii) * KPITCH + 2 * dh];
#pragma unroll
            for (int jj = 0; jj < 4; jj++) kv[jj] = *(float2*)&sk[(L + 32 * jj) * KPITCH + 2 * dh];
#pragma unroll
            for (int ii = 0; ii < 4; ii++)
#pragma unroll
                for (int jj = 0; jj < 4; jj++) {
                    acc[ii][jj] += qv[ii].x * kv[jj].x;
                    acc[ii][jj] += qv[ii].y * kv[jj].y;
                }
        }
        float rsc[4];
#pragma unroll
        for (int jj = 0; jj < 4; jj++) rsc[jj] = rn[L + 32 * jj] * 0.125f;
#pragma unroll
        for (int ii = 0; ii < 4; ii++) {
            int i = i0 + 16 * ii;
            int ti = skt[i];
#pragma unroll
            for (int jj = 0; jj < 4; jj++) {
                int j = L + 32 * jj;
                float s = acc[ii][jj] * rsc[jj];
                if (ti == skt[j]) s = -5e4f;
                sp[i * PPITCH + j] = s;
            }
        }
    }
    __syncthreads();

    // warp-parallel row softmax + lse (validated round 14)
#pragma unroll
    for (int r = 0; r < 8; r++) {
        int i = w + 8 * r;
        float v[4];
#pragma unroll
        for (int q = 0; q < 4; q++) v[q] = sp[i * PPITCH + L + 32 * q];
        float m = fmaxf(fmaxf(v[0], v[1]), fmaxf(v[2], v[3]));
#pragma unroll
        for (int o = 16; o > 0; o >>= 1) m = fmaxf(m, __shfl_xor_sync(0xffffffffu, m, o));
        float s = 0.f;
#pragma unroll
        for (int q = 0; q < 4; q++) { v[q] = expf(v[q] - m); s += v[q]; }
#pragma unroll
        for (int o = 16; o > 0; o >>= 1) s += __shfl_xor_sync(0xffffffffu, s, o);
        float inv = 1.f / s;
#pragma unroll
        for (int q = 0; q < 4; q++) sp[i * PPITCH + L + 32 * q] = v[q] * inv;
        if (L == 0) slse[i] = m + logf(s);
    }
    __syncthreads();

    // o = P @ V: float2 prob loads (j-pairs), j-ascending scalar accumulation
#pragma unroll
    for (int p = 0; p < 2; p++) {
        int i0 = w + 8 * p;
        float a0[4], a1[4];
#pragma unroll
        for (int ii = 0; ii < 4; ii++) { a0[ii] = 0.f; a1[ii] = 0.f; }
        for (int j2 = 0; j2 < 64; j2++) {
            int j = 2 * j2;
            float v00 = sv[j * KPITCH + L];
            float v01 = sv[j * KPITCH + L + 32];
            float v10 = sv[(j + 1) * KPITCH + L];
            float v11 = sv[(j + 1) * KPITCH + L + 32];
#pragma unroll
            for (int ii = 0; ii < 4; ii++) {
                float2 pv = *(float2*)&sp[(i0 + 16 * ii) * PPITCH + j];
                a0[ii] += pv.x * v00;
                a1[ii] += pv.x * v01;
                a0[ii] += pv.y * v10;
                a1[ii] += pv.y * v11;
            }
        }
#pragma unroll
        for (int ii = 0; ii < 4; ii++) {
            int i = i0 + 16 * ii;
            size_t ob = ((size_t)bh * NT_ + sqt[i]) * DH_;
            g_o[ob + L]      = a0[ii];
            g_o[ob + L + 32] = a1[ii];
        }
    }
    if (tid < 64) g_lse[(size_t)bh * NT_ + sqt[tid]] = slse[tid];
}

// ---------------- combine NHASH rounds (softmax over lse weights) ----------------
__global__ void combine_kernel()
{
    int gtid = blockIdx.x * blockDim.x + threadIdx.x;
    int w = gtid >> 5;
    int lane = gtid & 31;
    if (w >= BH_ * T_) return;
    int bh = w >> 12, t = w & (T_ - 1);
    int b = bh >> 3, head = bh & 7;
    float l[NHASH_];
    float m = -1e30f;
#pragma unroll
    for (int h = 0; h < NHASH_; h++) { l[h] = g_lse[(size_t)bh * NT_ + h * T_ + t]; m = fmaxf(m, l[h]); }
    float s = 0.f;
#pragma unroll
    for (int h = 0; h < NHASH_; h++) { l[h] = expf(l[h] - m); s += l[h]; }
    float inv = 1.f / s;
#pragma unroll
    for (int k = 0; k < 2; k++) {
        int d = lane + 32 * k;
        float acc = 0.f;
#pragma unroll
        for (int h = 0; h < NHASH_; h++)
            acc += l[h] * g_o[((size_t)bh * NT_ + h * T_ + t) * DH_ + d];
        g_attn[((size_t)(b * T_ + t)) * DIM_ + head * DH_ + d] = acc * inv;
    }
}

// ---------------- host launch ----------------
extern "C" void kernel_launch(void* const* d_in, const int* in_sizes, int n_in,
                              void* d_out, int out_size)
{
    (void)in_sizes; (void)n_in; (void)out_size;
    const int*   X    = (const int*)  d_in[0];
    const float* emb  = (const float*)d_in[1];
    const float* ax1  = (const float*)d_in[2];
    const float* ax2  = (const float*)d_in[3];
    const float* Wqk  = (const float*)d_in[4];
    const float* Wv   = (const float*)d_in[5];
    const float* Wo   = (const float*)d_in[6];
    const float* ln1g = (const float*)d_in[7];
    const float* ln1b = (const float*)d_in[8];
    const float* W1   = (const float*)d_in[9];
    const float* b1   = (const float*)d_in[10];
    const float* W2   = (const float*)d_in[11];
    const float* b2   = (const float*)d_in[12];
    const float* ln2g = (const float*)d_in[13];
    const float* ln2b = (const float*)d_in[14];
    const float* lnfg = (const float*)d_in[15];
    const float* lnfb = (const float*)d_in[16];
    const float* Wout = (const float*)d_in[17];
    const float* bout = (const float*)d_in[18];
    const float* rot  = (const float*)d_in[19];
    float* out = (float*)d_out;

    float *x1, *x2, *ln, *hid, *attn;
    cudaGetSymbolAddress((void**)&x1,   g_x1);
    cudaGetSymbolAddress((void**)&x2,   g_x2);
    cudaGetSymbolAddress((void**)&ln,   g_ln);
    cudaGetSymbolAddress((void**)&hid,  g_hid);
    cudaGetSymbolAddress((void**)&attn, g_attn);
    float *qkp, *vp;
    cudaGetSymbolAddress((void**)&qkp, g_qk);
    cudaGetSymbolAddress((void**)&vp,  g_v);

    const size_t ATTN_SMEM =
        (size_t)(2 * 128 * KPITCH + 64 * PPITCH + 128 + 64) * sizeof(float) + (64 + 128) * sizeof(int);
    cudaFuncSetAttribute(attn_kernel, cudaFuncAttributeMaxDynamicSharedMemorySize, (int)ATTN_SMEM);

    embed_kernel<<<(ROWS_ * DIM_) / 256, 256>>>(X, emb, ax1, ax2);

    for (int l = 0; l < DEPTH_; l++) {
        const float* Wqk_l = Wqk + (size_t)l * DIM_ * DIM_;
        const float* Wv_l  = Wv  + (size_t)l * DIM_ * DIM_;
        const float* Wo_l  = Wo  + (size_t)l * DIM_ * DIM_;
        const float* W1_l  = W1  + (size_t)l * DIM_ * HID_;
        const float* b1_l  = b1  + (size_t)l * HID_;
        const float* W2_l  = W2  + (size_t)l * HID_ * DIM_;
        const float* b2_l  = b2  + (size_t)l * DIM_;
        const float* rot_l = rot + (size_t)l * DH_ * NHASH_ * 32;

        // ---- attention: x1 += Attn(LN(x2)) @ Wo ----
        ln_kernel<<<ROWS_, 128>>>(x2, nullptr, ln1g + l * DIM_, ln1b + l * DIM_, ln);
        {
            // merged Wqk + Wv in one launch (z-dim selects weight/output)
            dim3 grid(DIM_ / 128, ROWS_ / 128, 2);
            sgemm<false, false, false, true><<<grid, 256>>>(
                ln, Wqk_l, nullptr, qkp, Wv_l, vp, ROWS_, DIM_, DIM_);
        }
        bucket_kernel<<<(BH_ * NHASH_ * T_) / 256, 256>>>(rot_l);
        hist_kernel<<<BH_, NCH_>>>();
        scatter_kernel<<<(BH_ * NCH_ * 32) / 256, 256>>>();
        attn_kernel<<<dim3(NCH_, BH_), 256, ATTN_SMEM>>>();
        combine_kernel<<<(BH_ * T_ * 32) / 256, 256>>>();
        {
            dim3 grid(DIM_ / 128, ROWS_ / 128, 1);
            sgemm<false, false, true, false><<<grid, 256>>>(
                attn, Wo_l, nullptr, x1, nullptr, nullptr, ROWS_, DIM_, DIM_);
        }

        // ---- feed-forward: x2 += W2 @ gelu(W1 @ LN(x1) + b1) + b2 ----
        ln_kernel<<<ROWS_, 128>>>(x1, nullptr, ln2g + l * DIM_, ln2b + l * DIM_, ln);
        {
            dim3 grid1(HID_ / 128, ROWS_ / 128, 1);
            sgemm<true, true, false, false><<<grid1, 256>>>(
                ln, W1_l, b1_l, hid, nullptr, nullptr, ROWS_, HID_, DIM_);
            dim3 grid2(DIM_ / 128, ROWS_ / 128, 1);
            sgemm<true, false, true, false><<<grid2, 256>>>(
                hid, W2_l, b2_l, x2, nullptr, nullptr, ROWS_, DIM_, HID_);
        }
    }

    // final: LN(0.5*(x1+x2)) @ Wout + bout
    ln_kernel<<<ROWS_, 128>>>(x1, x2, lnfg, lnfb, ln);
    {
        dim3 grid((TAGS_ + 63) / 64, ROWS_ / 64);
        gemm_small<true><<<grid, 256>>>(ln, Wout, bout, out, ROWS_, TAGS_, DIM_);
    }
}

// round 17
// speedup vs baseline: 1.1165x; 1.0340x over previous
#include <cuda_runtime.h>
#include <math.h>
#include <stdint.h>

// ---------------- problem constants ----------------
#define B_      2
#define T_      4096
#define DIM_    512
#define H_      8
#define DH_     64
#define NHASH_  8
#define NB_     64
#define BUCKET_ 64
#define NCH_    512          // NHASH * NB
#define BH_     16           // B * H
#define HID_    2048
#define TAGS_   17
#define NT_     32768        // NHASH * T
#define ROWS_   8192         // B * T
#define DEPTH_  2

// ---------------- scratch (device globals; no allocation allowed) ----------------
__device__ float g_x1[ROWS_ * DIM_];
__device__ float g_x2[ROWS_ * DIM_];
__device__ float g_ln[ROWS_ * DIM_];
__device__ float g_qk[ROWS_ * DIM_];
__device__ float g_v [ROWS_ * DIM_];
__device__ float g_attn[ROWS_ * DIM_];
__device__ float g_hid[ROWS_ * HID_];
__device__ int   g_buckets[BH_ * NT_];
__device__ int   g_offsets[BH_ * NCH_];
__device__ int   g_sidx[BH_ * NT_];
__device__ float g_o[(size_t)BH_ * NT_ * DH_];
__device__ float g_lse[BH_ * NT_];

// ---------------- embedding + axial positions ----------------
__global__ void embed_kernel(const int* __restrict__ X, const float* __restrict__ emb,
                             const float* __restrict__ ax1, const float* __restrict__ ax2)
{
    int idx = blockIdx.x * blockDim.x + threadIdx.x;
    if (idx >= ROWS_ * DIM_) return;
    int dcol = idx & (DIM_ - 1);
    int bt   = idx >> 9;
    int t    = bt & (T_ - 1);
    float val = emb[(size_t)X[bt] * DIM_ + dcol];
    if (dcol < 256) val += ax1[(t >> 6) * 256 + dcol];
    else            val += ax2[(t & 63) * 256 + (dcol - 256)];
    g_x1[idx] = val;
    g_x2[idx] = val;
}

// ---------------- layernorm (optionally y = LN(0.5*(x+xb))) ----------------
__global__ void ln_kernel(const float* __restrict__ x, const float* __restrict__ xb,
                          const float* __restrict__ g, const float* __restrict__ bt,
                          float* __restrict__ y)
{
    int row = blockIdx.x;
    int tid = threadIdx.x;           // 128
    const float* xr = x + (size_t)row * DIM_;
    float v[4];
    float s = 0.f;
#pragma unroll
    for (int k = 0; k < 4; k++) {
        int col = tid + 128 * k;
        float val = xr[col];
        if (xb) val = 0.5f * (val + xb[(size_t)row * DIM_ + col]);
        v[k] = val; s += val;
    }
    __shared__ float red[128];
    red[tid] = s; __syncthreads();
    for (int o = 64; o > 0; o >>= 1) { if (tid < o) red[tid] += red[tid + o]; __syncthreads(); }
    float mean = red[0] * (1.0f / DIM_);
    __syncthreads();
    float sq = 0.f;
#pragma unroll
    for (int k = 0; k < 4; k++) { float d = v[k] - mean; sq += d * d; }
    red[tid] = sq; __syncthreads();
    for (int o = 64; o > 0; o >>= 1) { if (tid < o) red[tid] += red[tid + o]; __syncthreads(); }
    float rstd = rsqrtf(red[0] * (1.0f / DIM_) + 1e-5f);
#pragma unroll
    for (int k = 0; k < 4; k++) {
        int col = tid + 128 * k;
        y[(size_t)row * DIM_ + col] = (v[k] - mean) * rstd * g[col] + bt[col];
    }
}

// ---------------- f32x2 packed-FMA helpers (sm_103a) ----------------
__device__ __forceinline__ unsigned long long pack2(float x) {
    unsigned long long r;
    asm("mov.b64 %0, {%1, %1};" : "=l"(r) : "r"(__float_as_uint(x)));
    return r;
}
__device__ __forceinline__ void fma2(unsigned long long& c, unsigned long long a, unsigned long long b) {
    asm("fma.rn.f32x2 %0, %1, %2, %0;" : "+l"(c) : "l"(a), "l"(b));
}
__device__ __forceinline__ void unpack2(unsigned long long p, float& lo, float& hi) {
    uint32_t l, h;
    asm("mov.b64 {%0, %1}, %2;" : "=r"(l), "=r"(h) : "l"(p));
    lo = __uint_as_float(l); hi = __uint_as_float(h);
}

// ---------------- fast fp32 SGEMM (round-11 core, FROZEN numerics) + optional z-merge ----------------
#define SAPITCH 132
template<bool BIAS, bool GELU, bool ACC, bool DUAL>
__global__ __launch_bounds__(256) void sgemm(const float* __restrict__ A,
                                             const float* __restrict__ W,
                                             const float* __restrict__ bias,
                                             float* __restrict__ C,
                                             const float* __restrict__ Wb,
                                             float* __restrict__ Cb,
                                             int M, int N, int K)
{
    if (DUAL && blockIdx.z) { W = Wb; C = Cb; }

    __shared__ float As[16][SAPITCH];   // transposed: As[k][m]
    __shared__ float Bs[16][128];       // natural:   Bs[k][n]

    int bn = blockIdx.x * 128, bm = blockIdx.y * 128;
    int tid = threadIdx.x;
    int tx = tid & 15, ty = tid >> 4;

    unsigned long long acc2[8][4];
#pragma unroll
    for (int i = 0; i < 8; i++)
#pragma unroll
        for (int jp = 0; jp < 4; jp++) acc2[i][jp] = 0ULL;

    float4 pa[2], pb[2];
#pragma unroll
    for (int i = 0; i < 2; i++) {
        int idx = tid + 256 * i;
        int arow = idx >> 2, akc = (idx & 3) * 4;
        pa[i] = *(const float4*)&A[(size_t)(bm + arow) * K + akc];
        int bkk = idx >> 5, bn4 = idx & 31;
        pb[i] = *(const float4*)&W[(size_t)bkk * N + bn + bn4 * 4];
    }

    for (int k0 = 0; k0 < K; k0 += 16) {
        __syncthreads();
#pragma unroll
        for (int i = 0; i < 2; i++) {
            int idx = tid + 256 * i;
            int arow = idx >> 2, akc = (idx & 3) * 4;
            As[akc + 0][arow] = pa[i].x;
            As[akc + 1][arow] = pa[i].y;
            As[akc + 2][arow] = pa[i].z;
            As[akc + 3][arow] = pa[i].w;
            int bkk = idx >> 5, bn4 = idx & 31;
            *(float4*)&Bs[bkk][bn4 * 4] = pb[i];
        }
        __syncthreads();
        if (k0 + 16 < K) {
#pragma unroll
            for (int i = 0; i < 2; i++) {
                int idx = tid + 256 * i;
                int arow = idx >> 2, akc = (idx & 3) * 4;
                pa[i] = *(const float4*)&A[(size_t)(bm + arow) * K + k0 + 16 + akc];
                int bkk = idx >> 5, bn4 = idx & 31;
                pb[i] = *(const float4*)&W[(size_t)(k0 + 16 + bkk) * N + bn + bn4 * 4];
            }
        }
#pragma unroll
        for (int kk = 0; kk < 16; kk++) {
            float4 a0 = *(float4*)&As[kk][ty * 4];
            float4 a1 = *(float4*)&As[kk][ty * 4 + 64];
            ulonglong2 b0 = *(ulonglong2*)&Bs[kk][tx * 4];
            ulonglong2 b1 = *(ulonglong2*)&Bs[kk][tx * 4 + 64];
            unsigned long long bp[4] = {b0.x, b0.y, b1.x, b1.y};
            float a[8] = {a0.x, a0.y, a0.z, a0.w, a1.x, a1.y, a1.z, a1.w};
#pragma unroll
            for (int i = 0; i < 8; i++) {
                unsigned long long ap = pack2(a[i]);
#pragma unroll
                for (int jp = 0; jp < 4; jp++) fma2(acc2[i][jp], ap, bp[jp]);
            }
        }
    }

#pragma unroll
    for (int ih = 0; ih < 2; ih++) {
#pragma unroll
        for (int i = 0; i < 4; i++) {
            int m = bm + ty * 4 + ih * 64 + i;
#pragma unroll
            for (int jh = 0; jh < 2; jh++) {
                int n = bn + tx * 4 + jh * 64;
#pragma unroll
                for (int jp = 0; jp < 2; jp++) {
                    float v0, v1;
                    unpack2(acc2[ih * 4 + i][jh * 2 + jp], v0, v1);
                    int nn = n + jp * 2;
                    if (BIAS) { v0 += bias[nn]; v1 += bias[nn + 1]; }
                    if (GELU) {
                        float x = v0;
                        v0 = 0.5f * x * (1.f + tanhf(0.7978845608028654f * (x + 0.044715f * x * x * x)));
                        x = v1;
                        v1 = 0.5f * x * (1.f + tanhf(0.7978845608028654f * (x + 0.044715f * x * x * x)));
                    }
                    size_t idx = (size_t)m * N + nn;
                    if (ACC) { C[idx] += v0; C[idx + 1] += v1; }
                    else     { C[idx]  = v0; C[idx + 1]  = v1; }
                }
            }
        }
    }
}

// ---------------- scalar GEMM (only used for N=17 output head) ----------------
template<bool BIAS>
__global__ void gemm_small(const float* __restrict__ A, const float* __restrict__ W,
                           const float* __restrict__ bias, float* __restrict__ C,
                           int M, int N, int K)
{
    __shared__ float As[64][17];
    __shared__ float Bs[16][65];
    int bn = blockIdx.x * 64, bm = blockIdx.y * 64;
    int tid = threadIdx.x;
    int tx = tid & 15, ty = tid >> 4;
    int m0 = ty * 4, n0 = tx * 4;
    float acc[4][4] = {};
    for (int k0 = 0; k0 < K; k0 += 16) {
#pragma unroll
        for (int i = 0; i < 4; i++) {
            int e = tid + 256 * i;
            int m = e >> 4, k = e & 15;
            As[m][k] = A[(size_t)(bm + m) * K + k0 + k];
            int kb = e >> 6, nb = e & 63;
            float w = 0.f;
            if (bn + nb < N) w = W[(size_t)(k0 + kb) * N + bn + nb];
            Bs[kb][nb] = w;
        }
        __syncthreads();
#pragma unroll
        for (int k = 0; k < 16; k++) {
            float a[4], b[4];
#pragma unroll
            for (int i = 0; i < 4; i++) a[i] = As[m0 + i][k];
#pragma unroll
            for (int j = 0; j < 4; j++) b[j] = Bs[k][n0 + j];
#pragma unroll
            for (int i = 0; i < 4; i++)
#pragma unroll
                for (int j = 0; j < 4; j++) acc[i][j] += a[i] * b[j];
        }
        __syncthreads();
    }
#pragma unroll
    for (int i = 0; i < 4; i++) {
        int m = bm + m0 + i;
#pragma unroll
        for (int j = 0; j < 4; j++) {
            int n = bn + n0 + j;
            if (n < N) {
                float val = acc[i][j];
                if (BIAS) val += bias[n];
                C[(size_t)m * N + n] = val;
            }
        }
    }
}

// ---------------- LSH bucketing v4: rot staged in smem (broadcast reads) ----------------
// All 256 threads of a block share the same h (4096-long segments, 256-aligned
// blocks). rot slice for h (64x32 = 8KB) loaded cooperatively, then read as
// warp-uniform float4 broadcasts. Accumulation order identical to v3 => bit-exact.
__global__ __launch_bounds__(256) void bucket_kernel(const float* __restrict__ rot)
{
    __shared__ float srot[DH_][32];        // 8 KB

    int idx = blockIdx.x * blockDim.x + threadIdx.x;   // BH_*NHASH_*T_
    int tid = threadIdx.x;
    int t  = idx & (T_ - 1);
    int h  = (idx >> 12) & (NHASH_ - 1);   // uniform across the block
    int bh = idx >> 15;
    int b = bh >> 3, head = bh & 7;

    // cooperative load of rot[:, h, :]
    for (int e = tid; e < DH_ * 32; e += 256) {
        int d = e >> 5, r = e & 31;
        srot[d][r] = rot[((size_t)d * NHASH_ + h) * 32 + r];
    }
    __syncthreads();

    const float* q = g_qk + ((size_t)(b * T_ + t)) * DIM_ + head * DH_;

    float acc[32];
#pragma unroll
    for (int r = 0; r < 32; r++) acc[r] = 0.f;

#pragma unroll
    for (int d4 = 0; d4 < 16; d4++) {
        float4 q4 = *(const float4*)&q[d4 * 4];
#pragma unroll
        for (int dd = 0; dd < 4; dd++) {
            float qd = (dd == 0) ? q4.x : (dd == 1) ? q4.y : (dd == 2) ? q4.z : q4.w;
            const float4* rp = (const float4*)&srot[d4 * 4 + dd][0];
#pragma unroll
            for (int r4 = 0; r4 < 8; r4++) {
                float4 rv = rp[r4];
                acc[r4 * 4 + 0] += qd * rv.x;
                acc[r4 * 4 + 1] += qd * rv.y;
                acc[r4 * 4 + 2] += qd * rv.z;
                acc[r4 * 4 + 3] += qd * rv.w;
            }
        }
    }

    float best = acc[0]; int bi = 0;
#pragma unroll
    for (int r = 1; r < 32; r++) if (acc[r] > best) { best = acc[r]; bi = r; }
#pragma unroll
    for (int r = 0; r < 32; r++) { float v2 = -acc[r]; if (v2 > best) { best = v2; bi = r + 32; } }
    g_buckets[bh * NT_ + h * T_ + t] = bi + h * NB_;
}

// ---------------- histogram + parallel exclusive scan per bh ----------------
__global__ void hist_kernel()
{
    int bh = blockIdx.x;
    __shared__ int cnt[NCH_];
    __shared__ int scn[NCH_];
    int tid = threadIdx.x;                 // 512
    cnt[tid] = 0;
    __syncthreads();
    const int* bp = g_buckets + bh * NT_;
    for (int i = tid; i < NT_; i += NCH_) atomicAdd(&cnt[bp[i]], 1);
    __syncthreads();
    int own = cnt[tid];
    scn[tid] = own;
    __syncthreads();
    for (int o = 1; o < NCH_; o <<= 1) {
        int add = (tid >= o) ? scn[tid - o] : 0;
        __syncthreads();
        scn[tid] += add;
        __syncthreads();
    }
    g_offsets[bh * NCH_ + tid] = scn[tid] - own;   // exclusive
}

// ---------------- stable scatter: one WARP per (bh, global bucket) ----------------
__global__ void scatter_kernel()
{
    int w = (blockIdx.x * blockDim.x + threadIdx.x) >> 5;   // BH_*NCH_ warps
    int lane = threadIdx.x & 31;
    if (w >= BH_ * NCH_) return;
    int bh = w >> 9, gb = w & (NCH_ - 1);
    int h = gb >> 6;
    int pos = g_offsets[bh * NCH_ + gb];
    const int* bk = g_buckets + bh * NT_ + h * T_;
    int base = bh * NT_;
    for (int t0 = 0; t0 < T_; t0 += 32) {
        int t = t0 + lane;
        bool m = (bk[t] == gb);
        unsigned mask = __ballot_sync(0xffffffffu, m);
        if (m) {
            int r = __popc(mask & ((1u << lane) - 1u));
            g_sidx[base + pos + r] = h * T_ + t;
        }
        pos += __popc(mask);
    }
}

// ---------------- chunked LSH attention v6 (validated round 16, FROZEN) ----------------
#define KPITCH 66
#define PPITCH 130
__global__ __launch_bounds__(256, 2) void attn_kernel()
{
    extern __shared__ float sm[];
    float* sk   = sm;                        // 128*66 raw qk rows
    float* sv   = sk + 128 * KPITCH;         // 128*66
    float* sp   = sv + 128 * KPITCH;         // 64*130
    float* rn   = sp + 64 * PPITCH;          // 128 inverse key norms
    float* slse = rn + 128;                  // 64
    int*   sqt  = (int*)(slse + 64);         // 64
    int*   skt  = sqt + 64;                  // 128

    int c  = blockIdx.x;
    int bh = blockIdx.y;
    int b = bh >> 3, head = bh & 7;
    int tid = threadIdx.x;                   // 256
    int w = tid >> 5, L = tid & 31;
    const int* sidx_bh = g_sidx + bh * NT_;
    int pc = (c + NCH_ - 1) & (NCH_ - 1);

    if (tid < 64) {
        int si = sidx_bh[c * BUCKET_ + tid];
        sqt[tid] = si;
        skt[tid] = si & (T_ - 1);
    } else if (tid < 128) {
        int si = sidx_bh[pc * BUCKET_ + (tid - 64)];
        skt[tid] = si & (T_ - 1);
    }
    __syncthreads();

    for (int e = tid; e < 128 * 16; e += 256) {
        int j = e >> 4, d4 = e & 15;
        size_t base = ((size_t)(b * T_ + skt[j])) * DIM_ + head * DH_ + d4 * 4;
        float4 kq = *(const float4*)&g_qk[base];
        float4 vv = *(const float4*)&g_v[base];
        int o = j * KPITCH + d4 * 4;
        *(float2*)&sk[o]     = make_float2(kq.x, kq.y);
        *(float2*)&sk[o + 2] = make_float2(kq.z, kq.w);
        *(float2*)&sv[o]     = make_float2(vv.x, vv.y);
        *(float2*)&sv[o + 2] = make_float2(vv.z, vv.w);
    }
    __syncthreads();

    if (tid < 128) {
        float s = 0.f;
#pragma unroll
        for (int d = 0; d < 64; d++) { float x = sk[tid * KPITCH + d]; s += x * x; }
        rn[tid] = rsqrtf(s);
    }
    __syncthreads();

#pragma unroll
    for (int p = 0; p < 2; p++) {
        int i0 = w + 8 * p;
        float acc[4][4];
#pragma unroll
        for (int ii = 0; ii < 4; ii++)
#pragma unroll
            for (int jj = 0; jj < 4; jj++) acc[ii][jj] = 0.f;
        for (int dh = 0; dh < 32; dh++) {
            float2 qv[4], kv[4];
#pragma unroll
            for (int ii = 0; ii < 4; ii++) qv[ii] = *(float2*)&sk[(i0 + 16 * ii) * KPITCH + 2 * dh];
#pragma unroll
            for (int jj = 0; jj < 4; jj++) kv[jj] = *(float2*)&sk[(L + 32 * jj) * KPITCH + 2 * dh];
#pragma unroll
            for (int ii = 0; ii < 4; ii++)
#pragma unroll
                for (int jj = 0; jj < 4; jj++) {
                    acc[ii][jj] += qv[ii].x * kv[jj].x;
                    acc[ii][jj] += qv[ii].y * kv[jj].y;
                }
        }
        float rsc[4];
#pragma unroll
        for (int jj = 0; jj < 4; jj++) rsc[jj] = rn[L + 32 * jj] * 0.125f;
#pragma unroll
        for (int ii = 0; ii < 4; ii++) {
            int i = i0 + 16 * ii;
            int ti = skt[i];
#pragma unroll
            for (int jj = 0; jj < 4; jj++) {
                int j = L + 32 * jj;
                float s = acc[ii][jj] * rsc[jj];
                if (ti == skt[j]) s = -5e4f;
                sp[i * PPITCH + j] = s;
            }
        }
    }
    __syncthreads();

#pragma unroll
    for (int r = 0; r < 8; r++) {
        int i = w + 8 * r;
        float v[4];
#pragma unroll
        for (int q = 0; q < 4; q++) v[q] = sp[i * PPITCH + L + 32 * q];
        float m = fmaxf(fmaxf(v[0], v[1]), fmaxf(v[2], v[3]));
#pragma unroll
        for (int o = 16; o > 0; o >>= 1) m = fmaxf(m, __shfl_xor_sync(0xffffffffu, m, o));
        float s = 0.f;
#pragma unroll
        for (int q = 0; q < 4; q++) { v[q] = expf(v[q] - m); s += v[q]; }
#pragma unroll
        for (int o = 16; o > 0; o >>= 1) s += __shfl_xor_sync(0xffffffffu, s, o);
        float inv = 1.f / s;
#pragma unroll
        for (int q = 0; q < 4; q++) sp[i * PPITCH + L + 32 * q] = v[q] * inv;
        if (L == 0) slse[i] = m + logf(s);
    }
    __syncthreads();

#pragma unroll
    for (int p = 0; p < 2; p++) {
        int i0 = w + 8 * p;
        float a0[4], a1[4];
#pragma unroll
        for (int ii = 0; ii < 4; ii++) { a0[ii] = 0.f; a1[ii] = 0.f; }
        for (int j2 = 0; j2 < 64; j2++) {
            int j = 2 * j2;
            float v00 = sv[j * KPITCH + L];
            float v01 = sv[j * KPITCH + L + 32];
            float v10 = sv[(j + 1) * KPITCH + L];
            float v11 = sv[(j + 1) * KPITCH + L + 32];
#pragma unroll
            for (int ii = 0; ii < 4; ii++) {
                float2 pv = *(float2*)&sp[(i0 + 16 * ii) * PPITCH + j];
                a0[ii] += pv.x * v00;
                a1[ii] += pv.x * v01;
                a0[ii] += pv.y * v10;
                a1[ii] += pv.y * v11;
            }
        }
#pragma unroll
        for (int ii = 0; ii < 4; ii++) {
            int i = i0 + 16 * ii;
            size_t ob = ((size_t)bh * NT_ + sqt[i]) * DH_;
            g_o[ob + L]      = a0[ii];
            g_o[ob + L + 32] = a1[ii];
        }
    }
    if (tid < 64) g_lse[(size_t)bh * NT_ + sqt[tid]] = slse[tid];
}

// ---------------- combine NHASH rounds (softmax over lse weights) ----------------
__global__ void combine_kernel()
{
    int gtid = blockIdx.x * blockDim.x + threadIdx.x;
    int w = gtid >> 5;
    int lane = gtid & 31;
    if (w >= BH_ * T_) return;
    int bh = w >> 12, t = w & (T_ - 1);
    int b = bh >> 3, head = bh & 7;
    float l[NHASH_];
    float m = -1e30f;
#pragma unroll
    for (int h = 0; h < NHASH_; h++) { l[h] = g_lse[(size_t)bh * NT_ + h * T_ + t]; m = fmaxf(m, l[h]); }
    float s = 0.f;
#pragma unroll
    for (int h = 0; h < NHASH_; h++) { l[h] = expf(l[h] - m); s += l[h]; }
    float inv = 1.f / s;
#pragma unroll
    for (int k = 0; k < 2; k++) {
        int d = lane + 32 * k;
        float acc = 0.f;
#pragma unroll
        for (int h = 0; h < NHASH_; h++)
            acc += l[h] * g_o[((size_t)bh * NT_ + h * T_ + t) * DH_ + d];
        g_attn[((size_t)(b * T_ + t)) * DIM_ + head * DH_ + d] = acc * inv;
    }
}

// ---------------- host launch ----------------
extern "C" void kernel_launch(void* const* d_in, const int* in_sizes, int n_in,
                              void* d_out, int out_size)
{
    (void)in_sizes; (void)n_in; (void)out_size;
    const int*   X    = (const int*)  d_in[0];
    const float* emb  = (const float*)d_in[1];
    const float* ax1  = (const float*)d_in[2];
    const float* ax2  = (const float*)d_in[3];
    const float* Wqk  = (const float*)d_in[4];
    const float* Wv   = (const float*)d_in[5];
    const float* Wo   = (const float*)d_in[6];
    const float* ln1g = (const float*)d_in[7];
    const float* ln1b = (const float*)d_in[8];
    const float* W1   = (const float*)d_in[9];
    const float* b1   = (const float*)d_in[10];
    const float* W2   = (const float*)d_in[11];
    const float* b2   = (const float*)d_in[12];
    const float* ln2g = (const float*)d_in[13];
    const float* ln2b = (const float*)d_in[14];
    const float* lnfg = (const float*)d_in[15];
    const float* lnfb = (const float*)d_in[16];
    const float* Wout = (const float*)d_in[17];
    const float* bout = (const float*)d_in[18];
    const float* rot  = (const float*)d_in[19];
    float* out = (float*)d_out;

    float *x1, *x2, *ln, *hid, *attn;
    cudaGetSymbolAddress((void**)&x1,   g_x1);
    cudaGetSymbolAddress((void**)&x2,   g_x2);
    cudaGetSymbolAddress((void**)&ln,   g_ln);
    cudaGetSymbolAddress((void**)&hid,  g_hid);
    cudaGetSymbolAddress((void**)&attn, g_attn);
    float *qkp, *vp;
    cudaGetSymbolAddress((void**)&qkp, g_qk);
    cudaGetSymbolAddress((void**)&vp,  g_v);

    const size_t ATTN_SMEM =
        (size_t)(2 * 128 * KPITCH + 64 * PPITCH + 128 + 64) * sizeof(float) + (64 + 128) * sizeof(int);
    cudaFuncSetAttribute(attn_kernel, cudaFuncAttributeMaxDynamicSharedMemorySize, (int)ATTN_SMEM);

    embed_kernel<<<(ROWS_ * DIM_) / 256, 256>>>(X, emb, ax1, ax2);

    for (int l = 0; l < DEPTH_; l++) {
        const float* Wqk_l = Wqk + (size_t)l * DIM_ * DIM_;
        const float* Wv_l  = Wv  + (size_t)l * DIM_ * DIM_;
        const float* Wo_l  = Wo  + (size_t)l * DIM_ * DIM_;
        const float* W1_l  = W1  + (size_t)l * DIM_ * HID_;
        const float* b1_l  = b1  + (size_t)l * HID_;
        const float* W2_l  = W2  + (size_t)l * HID_ * DIM_;
        const float* b2_l  = b2  + (size_t)l * DIM_;
        const float* rot_l = rot + (size_t)l * DH_ * NHASH_ * 32;

        // ---- attention: x1 += Attn(LN(x2)) @ Wo ----
        ln_kernel<<<ROWS_, 128>>>(x2, nullptr, ln1g + l * DIM_, ln1b + l * DIM_, ln);
        {
            dim3 grid(DIM_ / 128, ROWS_ / 128, 2);
            sgemm<false, false, false, true><<<grid, 256>>>(
                ln, Wqk_l, nullptr, qkp, Wv_l, vp, ROWS_, DIM_, DIM_);
        }
        bucket_kernel<<<(BH_ * NHASH_ * T_) / 256, 256>>>(rot_l);
        hist_kernel<<<BH_, NCH_>>>();
        scatter_kernel<<<(BH_ * NCH_ * 32) / 256, 256>>>();
        attn_kernel<<<dim3(NCH_, BH_), 256, ATTN_SMEM>>>();
        combine_kernel<<<(BH_ * T_ * 32) / 256, 256>>>();
        {
            dim3 grid(DIM_ / 128, ROWS_ / 128, 1);
            sgemm<false, false, true, false><<<grid, 256>>>(
                attn, Wo_l, nullptr, x1, nullptr, nullptr, ROWS_, DIM_, DIM_);
        }

        // ---- feed-forward: x2 += W2 @ gelu(W1 @ LN(x1) + b1) + b2 ----
        ln_kernel<<<ROWS_, 128>>>(x1, nullptr, ln2g + l * DIM_, ln2b + l * DIM_, ln);
        {
            dim3 grid1(HID_ / 128, ROWS_ / 128, 1);
            sgemm<true, true, false, false><<<grid1, 256>>>(
                ln, W1_l, b1_l, hid, nullptr, nullptr, ROWS_, HID_, DIM_);
            dim3 grid2(DIM_ / 128, ROWS_ / 128, 1);
            sgemm<true, false, true, false><<<grid2, 256>>>(
                hid, W2_l, b2_l, x2, nullptr, nullptr, ROWS_, DIM_, HID_);
        }
    }

    // final: LN(0.5*(x1+x2)) @ Wout + bout
    ln_kernel<<<ROWS_, 128>>>(x1, x2, lnfg, lnfb, ln);
    {
        dim3 grid((TAGS_ + 63) / 64, ROWS_ / 64);
        gemm_small<true><<<grid, 256>>>(ln, Wout, bout, out, ROWS_, TAGS_, DIM_);
    }
}